// round 8
// baseline (speedup 1.0000x reference)
#include <cuda_runtime.h>
#include <cuda_bf16.h>
#include <math.h>

// TopkRouter: logits = X @ W^T + b ; top-8 ; masked softmax.
// X: [32768, 2048] f32, W: [64, 2048] f32, b: [64] f32
// out: probs [32768, 64] f32 then indices [32768, 8] (as f32).
//
// Numerics (FROZEN, matches XLA:CPU Eigen gebp bitwise): per output, serial
// ascending-k fp32 FMA within 320-wide K panels; master += panel at each
// boundary (k=320,...,1920); 128-wide remainder; bias added at the end.
//
// R8 perf changes (order-preserving):
//  - X smem reads vectorized over k: LDS.128 per token per 4 k-steps
//    (stride back to 36 for 16B alignment). LDS/k: 6 -> 2.25.
//  - Register-prefetch software pipeline: next tile's LDGs issued before
//    compute of current tile -> LDG latency hidden.

#define TOKENS 32768
#define EMBED 2048
#define NEXP 64
#define TOPK 8
#define TPB 128          // tokens per block
#define KT 32            // k tile
#define NTILES (EMBED / KT)
#define KC_TILES 10      // flush every 10 tiles => panel = 320 (Eigen cap)
#define XS_STRIDE 36     // 16B-aligned rows for LDS.128 over k
#define WS_STRIDE 68     // 64 + 4 pad, 16B-aligned rows
#define LG_STRIDE 65     // logits row stride (conflict-free column scans)

static __device__ __forceinline__ unsigned long long pack2(float x) {
    unsigned long long r;
    asm("mov.b64 %0, {%1, %1};" : "=l"(r) : "f"(x));
    return r;
}
static __device__ __forceinline__ unsigned long long ffma2(unsigned long long a,
                                                           unsigned long long b,
                                                           unsigned long long c) {
    unsigned long long d;
    asm("fma.rn.f32x2 %0, %1, %2, %3;" : "=l"(d) : "l"(a), "l"(b), "l"(c));
    return d;
}
static __device__ __forceinline__ unsigned long long fadd2(unsigned long long a,
                                                           unsigned long long b) {
    unsigned long long d;
    asm("add.rn.f32x2 %0, %1, %2;" : "=l"(d) : "l"(a), "l"(b));
    return d;
}
static __device__ __forceinline__ void unpack2(unsigned long long v, float& lo, float& hi) {
    asm("mov.b64 {%0, %1}, %2;" : "=f"(lo), "=f"(hi) : "l"(v));
}

// shared layout (floats):
//   [0, 8320)   union: { Xs[128*36]=4608 | Ws at +4608 (32*68=2176) } OR logits[128*65]
//   [8320, 9344)  sidx[128*8]
//   [9344, 9408)  sbias[64]
#define SMEM_FLOATS (8320 + 1024 + 64)

__global__ __launch_bounds__(256, 2)
void topk_router_kernel(const float* __restrict__ X,
                        const float* __restrict__ W,
                        const float* __restrict__ B,
                        float* __restrict__ probs_out,
                        float* __restrict__ idx_out) {
    __shared__ float smem[SMEM_FLOATS];
    float* Xs     = smem;               // 128 x 36
    float* Ws     = smem + 4608;        // 32 x 68 (transposed: [k][e]); 16B-aligned
    float* logits = smem;               // 128 x 65 (overlaps tiles)
    float* sidx   = smem + 8320;        // 128 x 8
    float* sbias  = smem + 9344;        // 64

    const int tid  = threadIdx.x;
    const int tok0 = blockIdx.x * TPB;

    if (tid < NEXP) sbias[tid] = B[tid];

    const int g = tid >> 3;   // token group: tokens 4g..4g+3
    const int h = tid & 7;    // expert groups: 4h..4h+3 and 4h+32..4h+35

    // per-thread gmem source addresses (fixed across tiles, advance by KT)
    const int xt = tid >> 3;          // token 0..127 for X loader
    const int xc = tid & 7;           // 4-float chunk 0..7
    const int we = tid >> 3;          // expert row (loader, idx<512)
    // loader lanes: X uses idx = tid + 256r (r=0..3) -> rows xt + 32r? No:
    // idx>>3 = (tid+256r)>>3 = xt + 32r, chunk same xc. W: idx = tid, tid+256.
    const float* Xg = X + (size_t)(tok0 + xt) * EMBED + 4 * xc;
    const float* Wg = W + (size_t)we * EMBED + 4 * xc;

    // two-level fp32 accumulation: mst += til at every 320-k panel boundary
    unsigned long long mst[4][4];
    unsigned long long til[4][4];
#pragma unroll
    for (int i = 0; i < 4; i++)
#pragma unroll
        for (int j = 0; j < 4; j++) { mst[i][j] = 0ull; til[i][j] = 0ull; }

    // prefetch registers: X 4 x float4 (rows xt+32r), W 2 x float4
    float4 xr[4];
    float4 wr_[2];

    // prologue: load tile 0
#pragma unroll
    for (int r = 0; r < 4; r++)
        xr[r] = *reinterpret_cast<const float4*>(Xg + (size_t)(32 * r) * EMBED);
#pragma unroll
    for (int r = 0; r < 2; r++)
        wr_[r] = *reinterpret_cast<const float4*>(Wg + (size_t)(32 * r) * EMBED);

    for (int t = 0; t < NTILES; t++) {
        const int k0 = t * KT;
        __syncthreads();
        // ---- store prefetched X tile (float4, stride 36) ----
#pragma unroll
        for (int r = 0; r < 4; r++) {
            *reinterpret_cast<float4*>(Xs + (xt + 32 * r) * XS_STRIDE + 4 * xc) = xr[r];
        }
        // ---- store prefetched W tile transposed: Ws[k][e] ----
#pragma unroll
        for (int r = 0; r < 2; r++) {
            int e = we + 32 * r;
            Ws[(4 * xc + 0) * WS_STRIDE + e] = wr_[r].x;
            Ws[(4 * xc + 1) * WS_STRIDE + e] = wr_[r].y;
            Ws[(4 * xc + 2) * WS_STRIDE + e] = wr_[r].z;
            Ws[(4 * xc + 3) * WS_STRIDE + e] = wr_[r].w;
        }
        __syncthreads();
        // ---- issue next tile's loads (latency hidden under compute) ----
        if (t + 1 < NTILES) {
            const float* Xn = Xg + (k0 + KT);
            const float* Wn = Wg + (k0 + KT);
#pragma unroll
            for (int r = 0; r < 4; r++)
                xr[r] = *reinterpret_cast<const float4*>(Xn + (size_t)(32 * r) * EMBED);
#pragma unroll
            for (int r = 0; r < 2; r++)
                wr_[r] = *reinterpret_cast<const float4*>(Wn + (size_t)(32 * r) * EMBED);
        }
        // ---- compute: serial ascending k within the panel ----
#pragma unroll
        for (int kk4 = 0; kk4 < KT; kk4 += 4) {
            // X: one LDS.128 per token covering k..k+3
            float4 xv0 = *reinterpret_cast<const float4*>(Xs + (4 * g + 0) * XS_STRIDE + kk4);
            float4 xv1 = *reinterpret_cast<const float4*>(Xs + (4 * g + 1) * XS_STRIDE + kk4);
            float4 xv2 = *reinterpret_cast<const float4*>(Xs + (4 * g + 2) * XS_STRIDE + kk4);
            float4 xv3 = *reinterpret_cast<const float4*>(Xs + (4 * g + 3) * XS_STRIDE + kk4);
#pragma unroll
            for (int u = 0; u < 4; u++) {
                const float* wrow = Ws + (kk4 + u) * WS_STRIDE;
                ulonglong2 wa = *reinterpret_cast<const ulonglong2*>(wrow + 4 * h);
                ulonglong2 wb = *reinterpret_cast<const ulonglong2*>(wrow + 32 + 4 * h);
                float x0 = (u == 0) ? xv0.x : (u == 1) ? xv0.y : (u == 2) ? xv0.z : xv0.w;
                float x1 = (u == 0) ? xv1.x : (u == 1) ? xv1.y : (u == 2) ? xv1.z : xv1.w;
                float x2 = (u == 0) ? xv2.x : (u == 1) ? xv2.y : (u == 2) ? xv2.z : xv2.w;
                float x3 = (u == 0) ? xv3.x : (u == 1) ? xv3.y : (u == 2) ? xv3.z : xv3.w;
                unsigned long long xx0 = pack2(x0);
                unsigned long long xx1 = pack2(x1);
                unsigned long long xx2 = pack2(x2);
                unsigned long long xx3 = pack2(x3);
                til[0][0] = ffma2(xx0, wa.x, til[0][0]);
                til[0][1] = ffma2(xx0, wa.y, til[0][1]);
                til[0][2] = ffma2(xx0, wb.x, til[0][2]);
                til[0][3] = ffma2(xx0, wb.y, til[0][3]);
                til[1][0] = ffma2(xx1, wa.x, til[1][0]);
                til[1][1] = ffma2(xx1, wa.y, til[1][1]);
                til[1][2] = ffma2(xx1, wb.x, til[1][2]);
                til[1][3] = ffma2(xx1, wb.y, til[1][3]);
                til[2][0] = ffma2(xx2, wa.x, til[2][0]);
                til[2][1] = ffma2(xx2, wa.y, til[2][1]);
                til[2][2] = ffma2(xx2, wb.x, til[2][2]);
                til[2][3] = ffma2(xx2, wb.y, til[2][3]);
                til[3][0] = ffma2(xx3, wa.x, til[3][0]);
                til[3][1] = ffma2(xx3, wa.y, til[3][1]);
                til[3][2] = ffma2(xx3, wb.x, til[3][2]);
                til[3][3] = ffma2(xx3, wb.y, til[3][3]);
            }
        }
        // ---- Eigen panel boundary: after tiles 9,19,...,59 (k=320,...,1920) ----
        if ((t + 1) % KC_TILES == 0) {
#pragma unroll
            for (int i = 0; i < 4; i++)
#pragma unroll
                for (int j = 0; j < 4; j++) {
                    mst[i][j] = fadd2(mst[i][j], til[i][j]);
                    til[i][j] = 0ull;
                }
        }
    }
    // final remainder panel (k = 1920..2047, 128 wide)
#pragma unroll
    for (int i = 0; i < 4; i++)
#pragma unroll
        for (int j = 0; j < 4; j++) mst[i][j] = fadd2(mst[i][j], til[i][j]);

    __syncthreads();   // all warps done reading tiles; safe to overwrite with logits

    // ---- bias add + stash logits in smem ----
#pragma unroll
    for (int i = 0; i < 4; i++) {
        int t = 4 * g + i;
#pragma unroll
        for (int j = 0; j < 4; j++) {
            int e = (j < 2) ? (4 * h + 2 * j) : (32 + 4 * h + 2 * (j - 2));
            float lo, hi;
            unpack2(mst[i][j], lo, hi);
            logits[t * LG_STRIDE + e]     = lo + sbias[e];
            logits[t * LG_STRIDE + e + 1] = hi + sbias[e + 1];
        }
    }
    __syncthreads();

    // ---- top-8 + masked softmax, one thread per token ----
    if (tid < TPB) {
        float* row = logits + tid * LG_STRIDE;
        float vals[TOPK];
        int   inds[TOPK];
#pragma unroll
        for (int s = 0; s < TOPK; s++) {
            float best = -INFINITY;
            int bi = 0;
            for (int j = 0; j < NEXP; j++) {
                float v = row[j];
                if (v > best) { best = v; bi = j; }   // strict > : lowest index on ties
            }
            vals[s] = best;
            inds[s] = bi;
            row[bi] = -INFINITY;
        }
        float m = vals[0];
        float e[TOPK];
        float sum = 0.0f;
#pragma unroll
        for (int s = 0; s < TOPK; s++) { e[s] = expf(vals[s] - m); sum += e[s]; }
        float inv = 1.0f / sum;
        for (int j = 0; j < NEXP; j++) row[j] = 0.0f;
#pragma unroll
        for (int s = 0; s < TOPK; s++) {
            row[inds[s]] = e[s] * inv;
            sidx[tid * TOPK + s] = (float)inds[s];
        }
    }
    __syncthreads();

    // ---- coalesced writes ----
    for (int i = tid; i < TPB * NEXP; i += 256) {
        int t = i >> 6;
        int e = i & 63;
        probs_out[(size_t)(tok0 + t) * NEXP + e] = logits[t * LG_STRIDE + e];
    }
    if (idx_out) {
        for (int i = tid; i < TPB * TOPK; i += 256) {
            idx_out[(size_t)tok0 * TOPK + i] = sidx[i];
        }
    }
}

extern "C" void kernel_launch(void* const* d_in, const int* in_sizes, int n_in,
                              void* d_out, int out_size) {
    const float* X = (const float*)d_in[0];
    const float* W = (const float*)d_in[1];
    const float* B = (const float*)d_in[2];
    float* out = (float*)d_out;

    const long long PROBS_ELEMS = (long long)TOKENS * NEXP;   // 2097152
    const long long IDX_ELEMS   = (long long)TOKENS * TOPK;   // 262144
    float* idx_out = nullptr;
    if ((long long)out_size >= PROBS_ELEMS + IDX_ELEMS) idx_out = out + PROBS_ELEMS;

    topk_router_kernel<<<TOKENS / TPB, 256>>>(X, W, B, out, idx_out);
}

// round 9
// speedup vs baseline: 1.1105x; 1.1105x over previous
#include <cuda_runtime.h>
#include <cuda_bf16.h>
#include <math.h>
#include <stdint.h>

// TopkRouter: logits = X @ W^T + b ; top-8 ; masked softmax.
// X: [32768, 2048] f32, W: [64, 2048] f32, b: [64] f32
// out: probs [32768, 64] f32 then indices [32768, 8] (as f32).
//
// Numerics (FROZEN, matches XLA:CPU Eigen gebp bitwise): per output, serial
// ascending-k fp32 FMA within 320-wide K panels; master += panel at each
// boundary (k=320,...,1920); 128-wide remainder; bias added at the end.
//
// R9: double-buffered tiles, X via cp.async (no regs), W via 8-reg prefetch,
// ONE barrier per tile. Compute core identical to R8 (order-preserving).

#define TOKENS 32768
#define EMBED 2048
#define NEXP 64
#define TOPK 8
#define TPB 128          // tokens per block
#define KT 32            // k tile
#define NTILES (EMBED / KT)
#define KC_TILES 10      // flush every 10 tiles => panel = 320 (Eigen cap)
#define XS_STRIDE 36     // 16B-aligned rows for LDS.128 over k
#define WS_STRIDE 68     // 64 + 4 pad, 16B-aligned rows
#define LG_STRIDE 65     // logits row stride

// dynamic smem layout (floats)
#define XBUF0 0
#define WBUF0 4608                    // 128*36
#define XBUF1 6784                    // +32*68
#define WBUF1 11392
#define SIDX_OFF 13568
#define SBIAS_OFF 14592
#define SMEM_FLOATS 14656             // 58624 bytes

static __device__ __forceinline__ unsigned long long pack2(float x) {
    unsigned long long r;
    asm("mov.b64 %0, {%1, %1};" : "=l"(r) : "f"(x));
    return r;
}
static __device__ __forceinline__ unsigned long long ffma2(unsigned long long a,
                                                           unsigned long long b,
                                                           unsigned long long c) {
    unsigned long long d;
    asm("fma.rn.f32x2 %0, %1, %2, %3;" : "=l"(d) : "l"(a), "l"(b), "l"(c));
    return d;
}
static __device__ __forceinline__ unsigned long long fadd2(unsigned long long a,
                                                           unsigned long long b) {
    unsigned long long d;
    asm("add.rn.f32x2 %0, %1, %2;" : "=l"(d) : "l"(a), "l"(b));
    return d;
}
static __device__ __forceinline__ void unpack2(unsigned long long v, float& lo, float& hi) {
    asm("mov.b64 {%0, %1}, %2;" : "=f"(lo), "=f"(hi) : "l"(v));
}
static __device__ __forceinline__ void cp_async16(uint32_t saddr, const void* g) {
    asm volatile("cp.async.cg.shared.global [%0], [%1], 16;" :: "r"(saddr), "l"(g));
}
static __device__ __forceinline__ void cp_commit() {
    asm volatile("cp.async.commit_group;" ::: "memory");
}
static __device__ __forceinline__ void cp_wait0() {
    asm volatile("cp.async.wait_group 0;" ::: "memory");
}

__global__ __launch_bounds__(256, 2)
void topk_router_kernel(const float* __restrict__ X,
                        const float* __restrict__ W,
                        const float* __restrict__ B,
                        float* __restrict__ probs_out,
                        float* __restrict__ idx_out) {
    extern __shared__ float smem[];
    float* sidx  = smem + SIDX_OFF;
    float* sbias = smem + SBIAS_OFF;
    float* logits = smem;             // overlaps tile buffers, used after GEMM

    const int tid  = threadIdx.x;
    const int tok0 = blockIdx.x * TPB;

    if (tid < NEXP) sbias[tid] = B[tid];

    const int g = tid >> 3;   // token group: tokens 4g..4g+3
    const int h = tid & 7;    // expert groups: 4h..4h+3 and 4h+32..4h+35

    // loader lanes
    const int xt = tid >> 3;          // token row base (0..31), rows xt+32r
    const int xc = tid & 7;           // 4-float chunk
    const float* Xg = X + (size_t)(tok0 + xt) * EMBED + 4 * xc;
    const float* Wg = W + (size_t)xt * EMBED + 4 * xc;   // expert rows xt, xt+32

    // smem byte addresses for the X cp.async destinations, both buffers
    const uint32_t smem_base_b = (uint32_t)__cvta_generic_to_shared(smem);
    uint32_t xdst[2][4];
#pragma unroll
    for (int b = 0; b < 2; b++)
#pragma unroll
        for (int r = 0; r < 4; r++)
            xdst[b][r] = smem_base_b +
                4u * ((b ? XBUF1 : XBUF0) + (uint32_t)(xt + 32 * r) * XS_STRIDE + 4 * xc);

    // accumulators
    unsigned long long mst[4][4];
    unsigned long long til[4][4];
#pragma unroll
    for (int i = 0; i < 4; i++)
#pragma unroll
        for (int j = 0; j < 4; j++) { mst[i][j] = 0ull; til[i][j] = 0ull; }

    float4 wr_[2];

    // prologue: async-load X tile 0, LDG W tile 0
#pragma unroll
    for (int r = 0; r < 4; r++)
        cp_async16(xdst[0][r], Xg + (size_t)(32 * r) * EMBED);
    cp_commit();
#pragma unroll
    for (int r = 0; r < 2; r++)
        wr_[r] = *reinterpret_cast<const float4*>(Wg + (size_t)(32 * r) * EMBED);

    for (int t = 0; t < NTILES; t++) {
        const int buf = t & 1;
        float* Xs = smem + (buf ? XBUF1 : XBUF0);
        float* Ws = smem + (buf ? WBUF1 : WBUF0);

        // store W tile t (other-parity buffer than the one being computed now)
#pragma unroll
        for (int r = 0; r < 2; r++) {
            int e = xt + 32 * r;
            Ws[(4 * xc + 0) * WS_STRIDE + e] = wr_[r].x;
            Ws[(4 * xc + 1) * WS_STRIDE + e] = wr_[r].y;
            Ws[(4 * xc + 2) * WS_STRIDE + e] = wr_[r].z;
            Ws[(4 * xc + 3) * WS_STRIDE + e] = wr_[r].w;
        }

        cp_wait0();           // X tile t landed (this thread's group)
        __syncthreads();      // all threads: tile t visible, tile t-1 compute done

        // issue next tile's loads (hidden under compute of tile t)
        if (t + 1 < NTILES) {
            const float* Xn = Xg + (size_t)(t + 1) * KT;
            const float* Wn = Wg + (size_t)(t + 1) * KT;
#pragma unroll
            for (int r = 0; r < 4; r++)
                cp_async16(xdst[(t + 1) & 1][r], Xn + (size_t)(32 * r) * EMBED);
            cp_commit();
#pragma unroll
            for (int r = 0; r < 2; r++)
                wr_[r] = *reinterpret_cast<const float4*>(Wn + (size_t)(32 * r) * EMBED);
        }

        // ---- compute: serial ascending k within the panel ----
#pragma unroll
        for (int kk4 = 0; kk4 < KT; kk4 += 4) {
            float4 xv0 = *reinterpret_cast<const float4*>(Xs + (4 * g + 0) * XS_STRIDE + kk4);
            float4 xv1 = *reinterpret_cast<const float4*>(Xs + (4 * g + 1) * XS_STRIDE + kk4);
            float4 xv2 = *reinterpret_cast<const float4*>(Xs + (4 * g + 2) * XS_STRIDE + kk4);
            float4 xv3 = *reinterpret_cast<const float4*>(Xs + (4 * g + 3) * XS_STRIDE + kk4);
#pragma unroll
            for (int u = 0; u < 4; u++) {
                const float* wrow = Ws + (kk4 + u) * WS_STRIDE;
                ulonglong2 wa = *reinterpret_cast<const ulonglong2*>(wrow + 4 * h);
                ulonglong2 wb = *reinterpret_cast<const ulonglong2*>(wrow + 32 + 4 * h);
                float x0 = (u == 0) ? xv0.x : (u == 1) ? xv0.y : (u == 2) ? xv0.z : xv0.w;
                float x1 = (u == 0) ? xv1.x : (u == 1) ? xv1.y : (u == 2) ? xv1.z : xv1.w;
                float x2 = (u == 0) ? xv2.x : (u == 1) ? xv2.y : (u == 2) ? xv2.z : xv2.w;
                float x3 = (u == 0) ? xv3.x : (u == 1) ? xv3.y : (u == 2) ? xv3.z : xv3.w;
                unsigned long long xx0 = pack2(x0);
                unsigned long long xx1 = pack2(x1);
                unsigned long long xx2 = pack2(x2);
                unsigned long long xx3 = pack2(x3);
                til[0][0] = ffma2(xx0, wa.x, til[0][0]);
                til[0][1] = ffma2(xx0, wa.y, til[0][1]);
                til[0][2] = ffma2(xx0, wb.x, til[0][2]);
                til[0][3] = ffma2(xx0, wb.y, til[0][3]);
                til[1][0] = ffma2(xx1, wa.x, til[1][0]);
                til[1][1] = ffma2(xx1, wa.y, til[1][1]);
                til[1][2] = ffma2(xx1, wb.x, til[1][2]);
                til[1][3] = ffma2(xx1, wb.y, til[1][3]);
                til[2][0] = ffma2(xx2, wa.x, til[2][0]);
                til[2][1] = ffma2(xx2, wa.y, til[2][1]);
                til[2][2] = ffma2(xx2, wb.x, til[2][2]);
                til[2][3] = ffma2(xx2, wb.y, til[2][3]);
                til[3][0] = ffma2(xx3, wa.x, til[3][0]);
                til[3][1] = ffma2(xx3, wa.y, til[3][1]);
                til[3][2] = ffma2(xx3, wb.x, til[3][2]);
                til[3][3] = ffma2(xx3, wb.y, til[3][3]);
            }
        }
        // ---- Eigen panel boundary (k=320,640,...,1920) ----
        if ((t + 1) % KC_TILES == 0) {
#pragma unroll
            for (int i = 0; i < 4; i++)
#pragma unroll
                for (int j = 0; j < 4; j++) {
                    mst[i][j] = fadd2(mst[i][j], til[i][j]);
                    til[i][j] = 0ull;
                }
        }
    }
    // final remainder panel (k = 1920..2047)
#pragma unroll
    for (int i = 0; i < 4; i++)
#pragma unroll
        for (int j = 0; j < 4; j++) mst[i][j] = fadd2(mst[i][j], til[i][j]);

    __syncthreads();   // tiles dead; reuse smem for logits

    // ---- bias add + stash logits ----
#pragma unroll
    for (int i = 0; i < 4; i++) {
        int t = 4 * g + i;
#pragma unroll
        for (int j = 0; j < 4; j++) {
            int e = (j < 2) ? (4 * h + 2 * j) : (32 + 4 * h + 2 * (j - 2));
            float lo, hi;
            unpack2(mst[i][j], lo, hi);
            logits[t * LG_STRIDE + e]     = lo + sbias[e];
            logits[t * LG_STRIDE + e + 1] = hi + sbias[e + 1];
        }
    }
    __syncthreads();

    // ---- top-8 + masked softmax, one thread per token ----
    if (tid < TPB) {
        float* row = logits + tid * LG_STRIDE;
        float vals[TOPK];
        int   inds[TOPK];
#pragma unroll
        for (int s = 0; s < TOPK; s++) {
            float best = -INFINITY;
            int bi = 0;
            for (int j = 0; j < NEXP; j++) {
                float v = row[j];
                if (v > best) { best = v; bi = j; }   // strict > : lowest index wins ties
            }
            vals[s] = best;
            inds[s] = bi;
            row[bi] = -INFINITY;
        }
        float m = vals[0];
        float e[TOPK];
        float sum = 0.0f;
#pragma unroll
        for (int s = 0; s < TOPK; s++) { e[s] = expf(vals[s] - m); sum += e[s]; }
        float inv = 1.0f / sum;
        for (int j = 0; j < NEXP; j++) row[j] = 0.0f;
#pragma unroll
        for (int s = 0; s < TOPK; s++) {
            row[inds[s]] = e[s] * inv;
            sidx[tid * TOPK + s] = (float)inds[s];
        }
    }
    __syncthreads();

    // ---- coalesced writes ----
    for (int i = tid; i < TPB * NEXP; i += 256) {
        int t = i >> 6;
        int e = i & 63;
        probs_out[(size_t)(tok0 + t) * NEXP + e] = logits[t * LG_STRIDE + e];
    }
    if (idx_out) {
        for (int i = tid; i < TPB * TOPK; i += 256) {
            idx_out[(size_t)tok0 * TOPK + i] = sidx[i];
        }
    }
}

extern "C" void kernel_launch(void* const* d_in, const int* in_sizes, int n_in,
                              void* d_out, int out_size) {
    const float* X = (const float*)d_in[0];
    const float* W = (const float*)d_in[1];
    const float* B = (const float*)d_in[2];
    float* out = (float*)d_out;

    const long long PROBS_ELEMS = (long long)TOKENS * NEXP;   // 2097152
    const long long IDX_ELEMS   = (long long)TOKENS * TOPK;   // 262144
    float* idx_out = nullptr;
    if ((long long)out_size >= PROBS_ELEMS + IDX_ELEMS) idx_out = out + PROBS_ELEMS;

    const int smem_bytes = SMEM_FLOATS * 4;
    cudaFuncSetAttribute(topk_router_kernel,
                         cudaFuncAttributeMaxDynamicSharedMemorySize, smem_bytes);
    topk_router_kernel<<<TOKENS / TPB, 256, smem_bytes>>>(X, W, B, out, idx_out);
}